// round 13
// baseline (speedup 1.0000x reference)
#include <cuda_runtime.h>
#include <math.h>
#include <stdint.h>

#define NTOK   2048
#define DIM    1024
#define HID    4096
#define NEXP   8
#define KTOP   2
#define NROWS  (NTOK*KTOP)
#define BK     32

#define SZ_STAGE 9216              // floats per pipeline stage (both GEMMs)
#define SMEM_BYTES (2*SZ_STAGE*4)  // 73728

// ---------------- scratch ----------------
__device__ int   g_idx[NTOK*KTOP];
__device__ float g_wgt[NTOK*KTOP];
__device__ int   g_base[NEXP];
__device__ int   g_cnt[NEXP];
__device__ int   g_cur[NEXP];
__device__ int   g_loc[NTOK*KTOP];
__device__ int   g_rowtok[NROWS];
__device__ float g_xr[(size_t)NTOK*DIM];   // tf32-rounded x
__device__ float g_h[(size_t)NROWS*HID];   // tf32-rounded bits
__device__ float g_y[(size_t)NROWS*DIM];

// ---------------- helpers ----------------
__device__ __forceinline__ uint32_t rna1(float f) {
    uint32_t u; asm("cvt.rna.tf32.f32 %0, %1;" : "=r"(u) : "f"(f)); return u;
}
__device__ __forceinline__ uint4 rna4(float4 v) {
    uint4 u; u.x=rna1(v.x); u.y=rna1(v.y); u.z=rna1(v.z); u.w=rna1(v.w); return u;
}
__device__ __forceinline__ void mma8(float* d, const uint32_t* a, const uint32_t* b) {
    asm volatile(
        "mma.sync.aligned.m16n8k8.row.col.f32.tf32.tf32.f32 "
        "{%0,%1,%2,%3}, {%4,%5,%6,%7}, {%8,%9}, {%0,%1,%2,%3};\n"
        : "+f"(d[0]), "+f"(d[1]), "+f"(d[2]), "+f"(d[3])
        : "r"(a[0]), "r"(a[1]), "r"(a[2]), "r"(a[3]), "r"(b[0]), "r"(b[1]));
}
#define FU(x) __float_as_uint(x)

// Permuted-k STS: one 8-chunk from two float4s (q0..3 in v0, q4..7 in v1)
// layout within chunk: [k0,k4,k1,k5,k2,k6,k3,k7] -> pair m holds (k=m, k=m+4)
__device__ __forceinline__ void sts_chunk(float* dst, float4 v0, float4 v1) {
    *(float2*)(dst + 0) = make_float2(v0.x, v1.x);
    *(float2*)(dst + 2) = make_float2(v0.y, v1.y);
    *(float2*)(dst + 4) = make_float2(v0.z, v1.z);
    *(float2*)(dst + 6) = make_float2(v0.w, v1.w);
}
__device__ __forceinline__ void sts_chunk_rna(float* dst, float4 v0, float4 v1) {
    uint4 u0 = rna4(v0), u1 = rna4(v1);
    *(float2*)(dst + 0) = make_float2(__uint_as_float(u0.x), __uint_as_float(u1.x));
    *(float2*)(dst + 2) = make_float2(__uint_as_float(u0.y), __uint_as_float(u1.y));
    *(float2*)(dst + 4) = make_float2(__uint_as_float(u0.z), __uint_as_float(u1.z));
    *(float2*)(dst + 6) = make_float2(__uint_as_float(u0.w), __uint_as_float(u1.w));
}

// ---------------- K0: gate + round x to tf32 ----------------
__global__ void k_gate(const float* __restrict__ x, const float* __restrict__ gw) {
    __shared__ float sg[NEXP*DIM];
    for (int i = threadIdx.x; i < NEXP*DIM; i += blockDim.x) sg[i] = gw[i];

    // round this block's 8 tokens of x into g_xr (2048 float4 / 256 thr)
    {
        size_t b0 = (size_t)blockIdx.x * 8 * DIM;
        for (int i = threadIdx.x; i < 8*DIM/4; i += blockDim.x)
            *(uint4*)&g_xr[b0 + (size_t)i*4] = rna4(*(const float4*)&x[b0 + (size_t)i*4]);
    }
    __syncthreads();

    int warp = threadIdx.x >> 5, lane = threadIdx.x & 31;
    int t = blockIdx.x * (blockDim.x >> 5) + warp;
    if (t >= NTOK) return;
    float s[NEXP];
    #pragma unroll
    for (int e = 0; e < NEXP; e++) s[e] = 0.f;
    const float* xt = x + (size_t)t * DIM;
    for (int i = lane; i < DIM; i += 32) {
        float xv = xt[i];
        #pragma unroll
        for (int e = 0; e < NEXP; e++) s[e] += xv * sg[e*DIM + i];
    }
    #pragma unroll
    for (int off = 16; off; off >>= 1)
        #pragma unroll
        for (int e = 0; e < NEXP; e++) s[e] += __shfl_xor_sync(0xffffffffu, s[e], off);
    if (lane == 0) {
        int i0 = 0; float v0 = s[0];
        #pragma unroll
        for (int e = 1; e < NEXP; e++) if (s[e] > v0) { v0 = s[e]; i0 = e; }
        int i1 = -1; float v1 = -1e30f;
        #pragma unroll
        for (int e = 0; e < NEXP; e++) if (e != i0 && s[e] > v1) { v1 = s[e]; i1 = e; }
        float w1 = 1.f / (1.f + expf(v0 - v1));
        g_idx[t*2+0] = i0;  g_idx[t*2+1] = i1;
        g_wgt[t*2+0] = 1.f - w1;  g_wgt[t*2+1] = w1;
    }
}

// ---------------- K1/K2: histogram + assign ----------------
__global__ void k_hist() {
    __shared__ int c[NEXP];
    if (threadIdx.x < NEXP) c[threadIdx.x] = 0;
    __syncthreads();
    for (int i = threadIdx.x; i < NTOK*KTOP; i += blockDim.x) atomicAdd(&c[g_idx[i]], 1);
    __syncthreads();
    if (threadIdx.x == 0) {
        int run = 0;
        #pragma unroll
        for (int e = 0; e < NEXP; e++) { g_base[e] = run; g_cnt[e] = c[e]; g_cur[e] = 0; run += c[e]; }
    }
}
__global__ void k_assign() {
    int t = blockIdx.x * blockDim.x + threadIdx.x;
    if (t >= NTOK) return;
    #pragma unroll
    for (int k = 0; k < KTOP; k++) {
        int e = g_idx[t*2+k];
        int p = atomicAdd(&g_cur[e], 1);
        int row = g_base[e] + p;
        g_loc[t*2+k] = row;
        g_rowtok[row] = t;
    }
}

// ================= GEMM1: h = silu(x W1^T) * (x W3^T) =====================
// CTA 128m x 64n (per operand), 8 warps = 4m x 2n, warp 32x32 per operand.
// Permuted-k smem + LDS.64 frags + register frag double-buffer.
__global__ __launch_bounds__(256) void k_ffn1(
    const float* __restrict__ xr, const float* __restrict__ w1, const float* __restrict__ w3)
{
    extern __shared__ float sm1[];
    int e = blockIdx.z, cnt = g_cnt[e], base = g_base[e];
    int m0 = blockIdx.y * 128;
    if (m0 >= cnt) return;
    int n0 = blockIdx.x * 64;
    int tid = threadIdx.x;

    // loader roles
    int ar = tid >> 1, ac = (tid & 1) * 16;
    bool aval = (m0 + ar) < cnt;
    int tok = aval ? g_rowtok[base + m0 + ar] : 0;
    const float* ap = xr + (size_t)tok * DIM + ac;
    int br = tid >> 2, bc = (tid & 3) * 8;
    const float* b1p = w1 + ((size_t)e*HID + n0 + br) * DIM + bc;
    const float* b3p = w3 + ((size_t)e*HID + n0 + br) * DIM + bc;

    // compute roles
    int lane = tid & 31, g = lane >> 2, tg = lane & 3;
    int w = tid >> 5;
    int wm = (w >> 1) * 32, wn = (w & 1) * 32;

    float acc1[2][4][4] = {}, acc3[2][4][4] = {};
    float4 va[4], vb1[2], vb3[2];
    float2 fa[2][2][2], fb1[2][4], fb3[2][4];   // [buf][...]

    // global fetch tile 0 + store to stage 0
    #pragma unroll
    for (int j = 0; j < 4; j++) va[j] = aval ? *(const float4*)(ap + j*4) : make_float4(0,0,0,0);
    vb1[0] = *(const float4*)(b1p);  vb1[1] = *(const float4*)(b1p + 4);
    vb3[0] = *(const float4*)(b3p);  vb3[1] = *(const float4*)(b3p + 4);
    {
        float* A = sm1; float* B1 = sm1 + 4608; float* B3 = sm1 + 6912;
        sts_chunk(&A[ar*36 + ac],     va[0], va[1]);   // xr pre-rounded
        sts_chunk(&A[ar*36 + ac + 8], va[2], va[3]);
        sts_chunk_rna(&B1[br*36 + bc], vb1[0], vb1[1]);
        sts_chunk_rna(&B3[br*36 + bc], vb3[0], vb3[1]);
    }

#define LDA1(buf, ksv) { \
    _Pragma("unroll") for (int f = 0; f < 2; f++) { \
        int r0 = wm + f*16 + g; \
        fa[buf][f][0] = *(const float2*)&A[ r0     *36 + (ksv)*8 + 2*tg]; \
        fa[buf][f][1] = *(const float2*)&A[(r0 + 8)*36 + (ksv)*8 + 2*tg]; } }
#define LDB1(buf, ksv) { \
    _Pragma("unroll") for (int j = 0; j < 4; j++) { \
        int n = wn + j*8 + g; \
        fb1[buf][j] = *(const float2*)&B1[n*36 + (ksv)*8 + 2*tg]; \
        fb3[buf][j] = *(const float2*)&B3[n*36 + (ksv)*8 + 2*tg]; } }
#define MMA1(buf) { \
    _Pragma("unroll") for (int f = 0; f < 2; f++) { \
        uint32_t a[4] = { FU(fa[buf][f][0].x), FU(fa[buf][f][1].x), \
                          FU(fa[buf][f][0].y), FU(fa[buf][f][1].y) }; \
        _Pragma("unroll") for (int j = 0; j < 4; j++) { \
            uint32_t b1r[2] = { FU(fb1[buf][j].x), FU(fb1[buf][j].y) }; \
            uint32_t b3r[2] = { FU(fb3[buf][j].x), FU(fb3[buf][j].y) }; \
            mma8(acc1[f][j], a, b1r); \
            mma8(acc3[f][j], a, b3r); } } }

    const int NIT = DIM/BK;
    for (int i = 0; i < NIT; i++) {
        __syncthreads();
        if (i + 1 < NIT) {
            int ko = (i + 1) * BK;
            #pragma unroll
            for (int j = 0; j < 4; j++) va[j] = aval ? *(const float4*)(ap + ko + j*4) : make_float4(0,0,0,0);
            vb1[0] = *(const float4*)(b1p + ko);  vb1[1] = *(const float4*)(b1p + ko + 4);
            vb3[0] = *(const float4*)(b3p + ko);  vb3[1] = *(const float4*)(b3p + ko + 4);
        }
        float* cs = sm1 + (i & 1) * SZ_STAGE;
        float* A = cs; float* B1 = cs + 4608; float* B3 = cs + 6912;
        LDA1(0, 0); LDB1(0, 0);
        #pragma unroll
        for (int ks = 0; ks < 4; ks++) {
            int cur = ks & 1, nxt = cur ^ 1;
            if (ks < 3) { LDA1(nxt, ks+1); LDB1(nxt, ks+1); }
            MMA1(cur);
        }
        if (i + 1 < NIT) {
            float* ns = sm1 + ((i + 1) & 1) * SZ_STAGE;
            float* An = ns; float* B1n = ns + 4608; float* B3n = ns + 6912;
            sts_chunk(&An[ar*36 + ac],     va[0], va[1]);
            sts_chunk(&An[ar*36 + ac + 8], va[2], va[3]);
            sts_chunk_rna(&B1n[br*36 + bc], vb1[0], vb1[1]);
            sts_chunk_rna(&B3n[br*36 + bc], vb3[0], vb3[1]);
        }
    }

    // epilogue: silu(d1)*d3 -> g_h (tf32-rounded)
    #pragma unroll
    for (int f = 0; f < 2; f++) {
        #pragma unroll
        for (int rr = 0; rr < 2; rr++) {
            int m = wm + f*16 + rr*8 + g;
            if (m0 + m >= cnt) continue;
            size_t rowb = (size_t)(base + m0 + m) * HID + n0 + wn;
            #pragma unroll
            for (int j = 0; j < 4; j++) {
                float v0 = acc1[f][j][rr*2+0], v1 = acc1[f][j][rr*2+1];
                float h0 = v0 / (1.f + __expf(-v0)) * acc3[f][j][rr*2+0];
                float h1 = v1 / (1.f + __expf(-v1)) * acc3[f][j][rr*2+1];
                *(uint2*)&g_h[rowb + j*8 + 2*tg] = make_uint2(rna1(h0), rna1(h1));
            }
        }
    }
}

// ================= GEMM2: y = h W2^T ======================================
// CTA 128x128, 8 warps = 4m x 2n, warp 32x64.
__global__ __launch_bounds__(256) void k_ffn2(const float* __restrict__ w2)
{
    extern __shared__ float sm2[];
    int e = blockIdx.z, cnt = g_cnt[e], base = g_base[e];
    int m0 = blockIdx.y * 128;
    if (m0 >= cnt) return;
    int n0 = blockIdx.x * 128;
    int tid = threadIdx.x;

    int ar = tid >> 1, ac = (tid & 1) * 16;
    bool aval = (m0 + ar) < cnt;
    int arow = aval ? (base + m0 + ar) : base;
    const float* ap = g_h + (size_t)arow * HID + ac;
    const float* bp = w2 + ((size_t)e*DIM + n0 + ar) * HID + ac;

    int lane = tid & 31, g = lane >> 2, tg = lane & 3;
    int w = tid >> 5;
    int wm = (w >> 1) * 32, wn = (w & 1) * 64;

    float acc[2][8][4] = {};
    float4 va[4], vb[4];
    float2 fa[2][2][2], fb[2][8];

    #pragma unroll
    for (int j = 0; j < 4; j++) {
        va[j] = aval ? *(const float4*)(ap + j*4) : make_float4(0,0,0,0);
        vb[j] = *(const float4*)(bp + j*4);
    }
    {
        float* A = sm2; float* B = sm2 + 4608;
        sts_chunk(&A[ar*36 + ac],     va[0], va[1]);    // g_h pre-rounded
        sts_chunk(&A[ar*36 + ac + 8], va[2], va[3]);
        sts_chunk_rna(&B[ar*36 + ac],     vb[0], vb[1]);
        sts_chunk_rna(&B[ar*36 + ac + 8], vb[2], vb[3]);
    }

#define LDA2(buf, ksv) { \
    _Pragma("unroll") for (int f = 0; f < 2; f++) { \
        int r0 = wm + f*16 + g; \
        fa[buf][f][0] = *(const float2*)&A[ r0     *36 + (ksv)*8 + 2*tg]; \
        fa[buf][f][1] = *(const float2*)&A[(r0 + 8)*36 + (ksv)*8 + 2*tg]; } }
#define LDB2(buf, ksv) { \
    _Pragma("unroll") for (int j = 0; j < 8; j++) { \
        int n = wn + j*8 + g; \
        fb[buf][j] = *(const float2*)&B[n*36 + (ksv)*8 + 2*tg]; } }
#define MMA2(buf) { \
    _Pragma("unroll") for (int f = 0; f < 2; f++) { \
        uint32_t a[4] = { FU(fa[buf][f][0].x), FU(fa[buf][f][1].x), \
                          FU(fa[buf][f][0].y), FU(fa[buf][f][1].y) }; \
        _Pragma("unroll") for (int j = 0; j < 8; j++) { \
            uint32_t br2[2] = { FU(fb[buf][j].x), FU(fb[buf][j].y) }; \
            mma8(acc[f][j], a, br2); } } }

    const int NIT = HID/BK;
    for (int i = 0; i < NIT; i++) {
        __syncthreads();
        if (i + 1 < NIT) {
            int ko = (i + 1) * BK;
            #pragma unroll
            for (int j = 0; j < 4; j++) {
                va[j] = aval ? *(const float4*)(ap + ko + j*4) : make_float4(0,0,0,0);
                vb[j] = *(const float4*)(bp + ko + j*4);
            }
        }
        float* cs = sm2 + (i & 1) * SZ_STAGE;
        float* A = cs; float* B = cs + 4608;
        LDA2(0, 0); LDB2(0, 0);
        #pragma unroll
        for (int ks = 0; ks < 4; ks++) {
            int cur = ks & 1, nxt = cur ^ 1;
            if (ks < 3) { LDA2(nxt, ks+1); LDB2(nxt, ks+1); }
            MMA2(cur);
        }
        if (i + 1 < NIT) {
            float* ns = sm2 + ((i + 1) & 1) * SZ_STAGE;
            float* An = ns; float* Bn = ns + 4608;
            sts_chunk(&An[ar*36 + ac],     va[0], va[1]);
            sts_chunk(&An[ar*36 + ac + 8], va[2], va[3]);
            sts_chunk_rna(&Bn[ar*36 + ac],     vb[0], vb[1]);
            sts_chunk_rna(&Bn[ar*36 + ac + 8], vb[2], vb[3]);
        }
    }

    #pragma unroll
    for (int f = 0; f < 2; f++) {
        #pragma unroll
        for (int rr = 0; rr < 2; rr++) {
            int m = wm + f*16 + rr*8 + g;
            if (m0 + m >= cnt) continue;
            size_t rowb = (size_t)(base + m0 + m) * DIM + n0 + wn;
            #pragma unroll
            for (int j = 0; j < 8; j++) {
                *(float2*)&g_y[rowb + j*8 + 2*tg] =
                    make_float2(acc[f][j][rr*2+0], acc[f][j][rr*2+1]);
            }
        }
    }
}

// ---------------- combine ----------------
__global__ void k_combine(float* __restrict__ out) {
    int i = blockIdx.x * blockDim.x + threadIdx.x;
    if (i >= NTOK * (DIM/4)) return;
    int t = i / (DIM/4);
    int dq = i % (DIM/4);
    float w0 = g_wgt[t*2+0], w1 = g_wgt[t*2+1];
    int r0 = g_loc[t*2+0], r1 = g_loc[t*2+1];
    float4 y0 = *(const float4*)&g_y[(size_t)r0*DIM + dq*4];
    float4 y1 = *(const float4*)&g_y[(size_t)r1*DIM + dq*4];
    float4 o;
    o.x = w0*y0.x + w1*y1.x; o.y = w0*y0.y + w1*y1.y;
    o.z = w0*y0.z + w1*y1.z; o.w = w0*y0.w + w1*y1.w;
    *(float4*)(out + (size_t)i*4) = o;
}

// ---------------- launcher ----------------
extern "C" void kernel_launch(void* const* d_in, const int* in_sizes, int n_in,
                              void* d_out, int out_size) {
    const float* x  = (const float*)d_in[0];
    const float* gw = (const float*)d_in[1];
    const float* w1 = (const float*)d_in[2];
    const float* w2 = (const float*)d_in[3];
    const float* w3 = (const float*)d_in[4];
    float* out = (float*)d_out;

    cudaFuncSetAttribute(k_ffn1, cudaFuncAttributeMaxDynamicSharedMemorySize, SMEM_BYTES);
    cudaFuncSetAttribute(k_ffn2, cudaFuncAttributeMaxDynamicSharedMemorySize, SMEM_BYTES);

    k_gate<<<NTOK/8, 256>>>(x, gw);
    k_hist<<<1, 256>>>();
    k_assign<<<NTOK/256, 256>>>();

    void* xr_ptr = nullptr;
    cudaGetSymbolAddress(&xr_ptr, g_xr);

    dim3 g1(HID/64, NTOK/128, NEXP);
    k_ffn1<<<g1, 256, SMEM_BYTES>>>((const float*)xr_ptr, w1, w3);

    dim3 g2(DIM/128, NTOK/128, NEXP);
    k_ffn2<<<g2, 256, SMEM_BYTES>>>(w2);

    k_combine<<<(NTOK*(DIM/4) + 255)/256, 256>>>(out);
}

// round 16
// speedup vs baseline: 1.3412x; 1.3412x over previous
#include <cuda_runtime.h>
#include <math.h>
#include <stdint.h>

#define NTOK   2048
#define DIM    1024
#define HID    4096
#define NEXP   8
#define KTOP   2
#define NROWS  (NTOK*KTOP)
#define BK     32

#define STAGE_B   36864              // bytes per stage (9216 floats), both GEMMs
#define SMEM_GEMM (3*STAGE_B)        // 110592 bytes, 3-stage pipeline
#define B1_OFF    18432              // ffn1: B1 at 4608 floats
#define B3_OFF    27648              // ffn1: B3 at 6912 floats
#define B2_OFF    18432              // ffn2: B at 4608 floats

// ---------------- scratch ----------------
__device__ int   g_idx[NTOK*KTOP];
__device__ float g_wgt[NTOK*KTOP];
__device__ int   g_base[NEXP];
__device__ int   g_cnt[NEXP];
__device__ int   g_cur[NEXP];
__device__ int   g_loc[NTOK*KTOP];
__device__ int   g_rowtok[NROWS];
__device__ float g_xr[(size_t)NTOK*DIM];   // tf32-rounded x
__device__ float g_h[(size_t)NROWS*HID];   // tf32-rounded bits
__device__ float g_y[(size_t)NROWS*DIM];

// ---------------- helpers ----------------
__device__ __forceinline__ uint32_t rna1(float f) {
    uint32_t u; asm("cvt.rna.tf32.f32 %0, %1;" : "=r"(u) : "f"(f)); return u;
}
__device__ __forceinline__ uint4 rna4(float4 v) {
    uint4 u; u.x=rna1(v.x); u.y=rna1(v.y); u.z=rna1(v.z); u.w=rna1(v.w); return u;
}
__device__ __forceinline__ uint32_t smem_u32(const void* p) {
    uint32_t a;
    asm("{ .reg .u64 t; cvta.to.shared.u64 t, %1; cvt.u32.u64 %0, t; }" : "=r"(a) : "l"(p));
    return a;
}
__device__ __forceinline__ void mma8(float* d, const uint32_t* a, const uint32_t* b) {
    asm volatile(
        "mma.sync.aligned.m16n8k8.row.col.f32.tf32.tf32.f32 "
        "{%0,%1,%2,%3}, {%4,%5,%6,%7}, {%8,%9}, {%0,%1,%2,%3};\n"
        : "+f"(d[0]), "+f"(d[1]), "+f"(d[2]), "+f"(d[3])
        : "r"(a[0]), "r"(a[1]), "r"(a[2]), "r"(a[3]), "r"(b[0]), "r"(b[1]));
}
__device__ __forceinline__ void ldsm4(uint32_t* r, uint32_t a) {
    asm volatile("ldmatrix.sync.aligned.m8n8.x4.shared.b16 {%0,%1,%2,%3}, [%4];"
        : "=r"(r[0]), "=r"(r[1]), "=r"(r[2]), "=r"(r[3]) : "r"(a));
}
__device__ __forceinline__ void cpa16z(uint32_t dst, const void* src, uint32_t sz) {
    asm volatile("cp.async.cg.shared.global [%0], [%1], 16, %2;" :: "r"(dst), "l"(src), "r"(sz));
}
__device__ __forceinline__ void cpa16(uint32_t dst, const void* src) {
    asm volatile("cp.async.cg.shared.global [%0], [%1], 16;" :: "r"(dst), "l"(src));
}
#define CP_COMMIT() asm volatile("cp.async.commit_group;" ::: "memory")
#define CP_WAIT1()  asm volatile("cp.async.wait_group 1;" ::: "memory")

// ---------------- K0: gate + round x to tf32 ----------------
__global__ void k_gate(const float* __restrict__ x, const float* __restrict__ gw) {
    __shared__ float sg[NEXP*DIM];
    for (int i = threadIdx.x; i < NEXP*DIM; i += blockDim.x) sg[i] = gw[i];
    {
        size_t b0 = (size_t)blockIdx.x * 8 * DIM;
        for (int i = threadIdx.x; i < 8*DIM/4; i += blockDim.x)
            *(uint4*)&g_xr[b0 + (size_t)i*4] = rna4(*(const float4*)&x[b0 + (size_t)i*4]);
    }
    __syncthreads();
    int warp = threadIdx.x >> 5, lane = threadIdx.x & 31;
    int t = blockIdx.x * (blockDim.x >> 5) + warp;
    if (t >= NTOK) return;
    float s[NEXP];
    #pragma unroll
    for (int e = 0; e < NEXP; e++) s[e] = 0.f;
    const float* xt = x + (size_t)t * DIM;
    for (int i = lane; i < DIM; i += 32) {
        float xv = xt[i];
        #pragma unroll
        for (int e = 0; e < NEXP; e++) s[e] += xv * sg[e*DIM + i];
    }
    #pragma unroll
    for (int off = 16; off; off >>= 1)
        #pragma unroll
        for (int e = 0; e < NEXP; e++) s[e] += __shfl_xor_sync(0xffffffffu, s[e], off);
    if (lane == 0) {
        int i0 = 0; float v0 = s[0];
        #pragma unroll
        for (int e = 1; e < NEXP; e++) if (s[e] > v0) { v0 = s[e]; i0 = e; }
        int i1 = -1; float v1 = -1e30f;
        #pragma unroll
        for (int e = 0; e < NEXP; e++) if (e != i0 && s[e] > v1) { v1 = s[e]; i1 = e; }
        float w1 = 1.f / (1.f + expf(v0 - v1));
        g_idx[t*2+0] = i0;  g_idx[t*2+1] = i1;
        g_wgt[t*2+0] = 1.f - w1;  g_wgt[t*2+1] = w1;
    }
}

// ---------------- K1/K2: histogram + assign ----------------
__global__ void k_hist() {
    __shared__ int c[NEXP];
    if (threadIdx.x < NEXP) c[threadIdx.x] = 0;
    __syncthreads();
    for (int i = threadIdx.x; i < NTOK*KTOP; i += blockDim.x) atomicAdd(&c[g_idx[i]], 1);
    __syncthreads();
    if (threadIdx.x == 0) {
        int run = 0;
        #pragma unroll
        for (int e = 0; e < NEXP; e++) { g_base[e] = run; g_cnt[e] = c[e]; g_cur[e] = 0; run += c[e]; }
    }
}
__global__ void k_assign() {
    int t = blockIdx.x * blockDim.x + threadIdx.x;
    if (t >= NTOK) return;
    #pragma unroll
    for (int k = 0; k < KTOP; k++) {
        int e = g_idx[t*2+k];
        int p = atomicAdd(&g_cur[e], 1);
        int row = g_base[e] + p;
        g_loc[t*2+k] = row;
        g_rowtok[row] = t;
    }
}

// ================= GEMM1: h = silu(x W1^T) * (x W3^T) =====================
// CTA 128m x 64n/operand, 8 warps = 4m x 2n, warp 32x32/operand.
// 3-stage cp.async pipeline, ldmatrix fragments, cvt.rna on B frags.
__global__ __launch_bounds__(256) void k_ffn1(
    const float* __restrict__ xr, const float* __restrict__ w1, const float* __restrict__ w3)
{
    extern __shared__ float sm[];
    uint32_t sb = smem_u32(sm);
    int e = blockIdx.z, cnt = g_cnt[e], base = g_base[e];
    int m0 = blockIdx.y * 128;
    if (m0 >= cnt) return;
    int n0 = blockIdx.x * 64;
    int tid = threadIdx.x;

    // ---- cp.async loader roles ----
    int ar = tid >> 1;                       // A row 0..127
    bool aval = (m0 + ar) < cnt;
    int tok = aval ? g_rowtok[base + m0 + ar] : 0;
    const float* ap = xr + (size_t)tok * DIM + (tid & 1) * 16;
    uint32_t a_dst  = sb + ar*144 + (tid & 1)*64;
    uint32_t asz = aval ? 16u : 0u;
    int br = tid >> 2, bcf = (tid & 3) * 8;  // B row 0..63, 8-float quarter
    const float* b1p = w1 + ((size_t)e*HID + n0 + br) * DIM + bcf;
    const float* b3p = w3 + ((size_t)e*HID + n0 + br) * DIM + bcf;
    uint32_t b1_dst = sb + B1_OFF + br*144 + bcf*4;
    uint32_t b3_dst = sb + B3_OFF + br*144 + bcf*4;

#define ISSUE1(s, ko) { uint32_t so = (uint32_t)(s)*STAGE_B; \
    cpa16z(a_dst+so,    ap+(ko),      asz); cpa16z(a_dst+so+16, ap+(ko)+4,  asz); \
    cpa16z(a_dst+so+32, ap+(ko)+8,    asz); cpa16z(a_dst+so+48, ap+(ko)+12, asz); \
    cpa16(b1_dst+so, b1p+(ko)); cpa16(b1_dst+so+16, b1p+(ko)+4); \
    cpa16(b3_dst+so, b3p+(ko)); cpa16(b3_dst+so+16, b3p+(ko)+4); \
    CP_COMMIT(); }

    // ---- compute roles ----
    int lane = tid & 31, w = tid >> 5;
    int wm = (w >> 1) * 32, wn = (w & 1) * 32;
    int g = lane >> 2, tg = lane & 3;
    // ldmatrix per-thread address offsets (bytes within stage)
    uint32_t a_lm = (uint32_t)((wm + (lane & 15))*144 + (lane >> 4)*16);
    uint32_t b_lm = (uint32_t)((((lane & 7) + ((lane >> 4) & 1)*8) + wn)*144 + ((lane >> 3) & 1)*16);

    float acc1[2][4][4] = {}, acc3[2][4][4] = {};
    uint32_t ua[2][2][4], ub1[2][2][4], ub3[2][2][4];

#define LDFA1(buf, st, ks) { \
    _Pragma("unroll") for (int f = 0; f < 2; f++) \
        ldsm4(ua[buf][f], sb + (st) + a_lm + (uint32_t)f*2304 + (uint32_t)(ks)*32); }
#define LDFB1(buf, st, ks) { uint32_t rr[4]; \
    _Pragma("unroll") for (int p = 0; p < 2; p++) { \
        ldsm4(rr, sb + (st) + B1_OFF + b_lm + (uint32_t)p*2304 + (uint32_t)(ks)*32); \
        _Pragma("unroll") for (int q = 0; q < 4; q++) ub1[buf][p][q] = rna1(__uint_as_float(rr[q])); \
        ldsm4(rr, sb + (st) + B3_OFF + b_lm + (uint32_t)p*2304 + (uint32_t)(ks)*32); \
        _Pragma("unroll") for (int q = 0; q < 4; q++) ub3[buf][p][q] = rna1(__uint_as_float(rr[q])); } }
#define MMA1K(buf) { \
    _Pragma("unroll") for (int f = 0; f < 2; f++) \
        _Pragma("unroll") for (int p = 0; p < 2; p++) { \
            mma8(acc1[f][2*p],   ua[buf][f], &ub1[buf][p][0]); \
            mma8(acc1[f][2*p+1], ua[buf][f], &ub1[buf][p][2]); \
            mma8(acc3[f][2*p],   ua[buf][f], &ub3[buf][p][0]); \
            mma8(acc3[f][2*p+1], ua[buf][f], &ub3[buf][p][2]); } }

    // prologue: stages 0,1 in flight
    ISSUE1(0, 0);
    ISSUE1(1, BK);

    const int NIT = DIM/BK;
    for (int i = 0; i < NIT; i++) {
        CP_WAIT1();
        __syncthreads();
        if (i + 2 < NIT) ISSUE1((i + 2) % 3, (i + 2) * BK);
        uint32_t st = (uint32_t)(i % 3) * STAGE_B;
        LDFA1(0, st, 0); LDFB1(0, st, 0);
        #pragma unroll
        for (int ks = 0; ks < 4; ks++) {
            int cur = ks & 1;
            if (ks < 3) { LDFA1(cur^1, st, ks+1); LDFB1(cur^1, st, ks+1); }
            MMA1K(cur);
        }
    }

    // epilogue: silu(d1)*d3 -> g_h (tf32-rounded)
    #pragma unroll
    for (int f = 0; f < 2; f++) {
        #pragma unroll
        for (int rr = 0; rr < 2; rr++) {
            int m = wm + f*16 + rr*8 + g;
            if (m0 + m >= cnt) continue;
            size_t rowb = (size_t)(base + m0 + m) * HID + n0 + wn;
            #pragma unroll
            for (int j = 0; j < 4; j++) {
                float v0 = acc1[f][j][rr*2+0], v1 = acc1[f][j][rr*2+1];
                float h0 = v0 / (1.f + __expf(-v0)) * acc3[f][j][rr*2+0];
                float h1 = v1 / (1.f + __expf(-v1)) * acc3[f][j][rr*2+1];
                *(uint2*)&g_h[rowb + j*8 + 2*tg] = make_uint2(rna1(h0), rna1(h1));
            }
        }
    }
}

// ================= GEMM2: y = h W2^T ======================================
// CTA 128x128, 8 warps = 4m x 2n, warp 32x64. Same pipeline.
__global__ __launch_bounds__(256) void k_ffn2(const float* __restrict__ w2)
{
    extern __shared__ float sm[];
    uint32_t sb = smem_u32(sm);
    int e = blockIdx.z, cnt = g_cnt[e], base = g_base[e];
    int m0 = blockIdx.y * 128;
    if (m0 >= cnt) return;
    int n0 = blockIdx.x * 128;
    int tid = threadIdx.x;

    int ar = tid >> 1;
    bool aval = (m0 + ar) < cnt;
    int arow = aval ? (base + m0 + ar) : base;
    const float* ap = g_h + (size_t)arow * HID + (tid & 1) * 16;
    const float* bp = w2 + ((size_t)e*DIM + n0 + ar) * HID + (tid & 1) * 16;
    uint32_t a_dst = sb + ar*144 + (tid & 1)*64;
    uint32_t b_dst = sb + B2_OFF + ar*144 + (tid & 1)*64;
    uint32_t asz = aval ? 16u : 0u;

#define ISSUE2(s, ko) { uint32_t so = (uint32_t)(s)*STAGE_B; \
    cpa16z(a_dst+so,    ap+(ko),      asz); cpa16z(a_dst+so+16, ap+(ko)+4,  asz); \
    cpa16z(a_dst+so+32, ap+(ko)+8,    asz); cpa16z(a_dst+so+48, ap+(ko)+12, asz); \
    cpa16(b_dst+so,    bp+(ko));    cpa16(b_dst+so+16, bp+(ko)+4); \
    cpa16(b_dst+so+32, bp+(ko)+8);  cpa16(b_dst+so+48, bp+(ko)+12); \
    CP_COMMIT(); }

    int lane = tid & 31, w = tid >> 5;
    int wm = (w >> 1) * 32, wn = (w & 1) * 64;
    int g = lane >> 2, tg = lane & 3;
    uint32_t a_lm = (uint32_t)((wm + (lane & 15))*144 + (lane >> 4)*16);
    uint32_t b_lm = (uint32_t)((((lane & 7) + ((lane >> 4) & 1)*8) + wn)*144 + ((lane >> 3) & 1)*16);

    float acc[2][8][4] = {};
    uint32_t ua[2][2][4], ub[2][4][4];

#define LDFA2(buf, st, ks) { \
    _Pragma("unroll") for (int f = 0; f < 2; f++) \
        ldsm4(ua[buf][f], sb + (st) + a_lm + (uint32_t)f*2304 + (uint32_t)(ks)*32); }
#define LDFB2(buf, st, ks) { uint32_t rr[4]; \
    _Pragma("unroll") for (int p = 0; p < 4; p++) { \
        ldsm4(rr, sb + (st) + B2_OFF + b_lm + (uint32_t)p*2304 + (uint32_t)(ks)*32); \
        _Pragma("unroll") for (int q = 0; q < 4; q++) ub[buf][p][q] = rna1(__uint_as_float(rr[q])); } }
#define MMA2K(buf) { \
    _Pragma("unroll") for (int f = 0; f < 2; f++) \
        _Pragma("unroll") for (int p = 0; p < 4; p++) { \
            mma8(acc[f][2*p],   ua[buf][f], &ub[buf][p][0]); \
            mma8(acc[f][2*p+1], ua[buf][f], &ub[buf][p][2]); } }

    ISSUE2(0, 0);
    ISSUE2(1, BK);

    const int NIT = HID/BK;
    for (int i = 0; i < NIT; i++) {
        CP_WAIT1();
        __syncthreads();
        if (i + 2 < NIT) ISSUE2((i + 2) % 3, (i + 2) * BK);
        uint32_t st = (uint32_t)(i % 3) * STAGE_B;
        LDFA2(0, st, 0); LDFB2(0, st, 0);
        #pragma unroll
        for (int ks = 0; ks < 4; ks++) {
            int cur = ks & 1;
            if (ks < 3) { LDFA2(cur^1, st, ks+1); LDFB2(cur^1, st, ks+1); }
            MMA2K(cur);
        }
    }

    #pragma unroll
    for (int f = 0; f < 2; f++) {
        #pragma unroll
        for (int rr = 0; rr < 2; rr++) {
            int m = wm + f*16 + rr*8 + g;
            if (m0 + m >= cnt) continue;
            size_t rowb = (size_t)(base + m0 + m) * DIM + n0 + wn;
            #pragma unroll
            for (int j = 0; j < 8; j++) {
                *(float2*)&g_y[rowb + j*8 + 2*tg] =
                    make_float2(acc[f][j][rr*2+0], acc[f][j][rr*2+1]);
            }
        }
    }
}

// ---------------- combine ----------------
__global__ void k_combine(float* __restrict__ out) {
    int i = blockIdx.x * blockDim.x + threadIdx.x;
    if (i >= NTOK * (DIM/4)) return;
    int t = i / (DIM/4);
    int dq = i % (DIM/4);
    float w0 = g_wgt[t*2+0], w1 = g_wgt[t*2+1];
    int r0 = g_loc[t*2+0], r1 = g_loc[t*2+1];
    float4 y0 = *(const float4*)&g_y[(size_t)r0*DIM + dq*4];
    float4 y1 = *(const float4*)&g_y[(size_t)r1*DIM + dq*4];
    float4 o;
    o.x = w0*y0.x + w1*y1.x; o.y = w0*y0.y + w1*y1.y;
    o.z = w0*y0.z + w1*y1.z; o.w = w0*y0.w + w1*y1.w;
    *(float4*)(out + (size_t)i*4) = o;
}

// ---------------- launcher ----------------
extern "C" void kernel_launch(void* const* d_in, const int* in_sizes, int n_in,
                              void* d_out, int out_size) {
    const float* x  = (const float*)d_in[0];
    const float* gw = (const float*)d_in[1];
    const float* w1 = (const float*)d_in[2];
    const float* w2 = (const float*)d_in[3];
    const float* w3 = (const float*)d_in[4];
    float* out = (float*)d_out;

    cudaFuncSetAttribute(k_ffn1, cudaFuncAttributeMaxDynamicSharedMemorySize, SMEM_GEMM);
    cudaFuncSetAttribute(k_ffn2, cudaFuncAttributeMaxDynamicSharedMemorySize, SMEM_GEMM);

    k_gate<<<NTOK/8, 256>>>(x, gw);
    k_hist<<<1, 256>>>();
    k_assign<<<NTOK/256, 256>>>();

    void* xr_ptr = nullptr;
    cudaGetSymbolAddress(&xr_ptr, g_xr);

    dim3 g1(HID/64, NTOK/128, NEXP);
    k_ffn1<<<g1, 256, SMEM_GEMM>>>((const float*)xr_ptr, w1, w3);

    dim3 g2(DIM/128, NTOK/128, NEXP);
    k_ffn2<<<g2, 256, SMEM_GEMM>>>(w2);

    k_combine<<<(NTOK*(DIM/4) + 255)/256, 256>>>(out);
}